// round 11
// baseline (speedup 1.0000x reference)
#include <cuda_runtime.h>
#include <cuda_fp16.h>
#include <stdint.h>

#define NN 8192
#define DH 64
#define KC 64              // j's per chunk
#define KSPLIT 2
#define KHALF (NN / KSPLIT)
#define NCH (KHALF / KC)   // 64 chunks
#define TPB 256
#define TILE_I 32
// smem: W tile 32x64 fp16 (4KB) x2, B tile 64x64 fp16 (8KB) x2
#define WOFF0 0
#define WOFF1 4096
#define BOFF0 8192
#define BOFF1 16384
#define SMEM_BYTES 24576

// ---------------- device scratch ----------------
__device__ uint8_t g_adjpB[NN * 1024];         // packed adjacency bits (8MB), byte granular
__device__ unsigned short g_WhT[DH * NN];      // Wh^T fp16 [64][8192]
__device__ uint2 g_iAC[NN];                    // {half2(exp(src)), half2(exp(.2src))}
__device__ unsigned short g_jB[NN];            // half exp(dst)
__device__ unsigned short g_jD[NN];            // half exp(.2 dst)
__device__ float g_part[KSPLIT * NN * DH];     // K-split partial numerators
__device__ float g_den[KSPLIT * NN];           // K-split partial denominators

// ---------------- helpers ----------------
__device__ __forceinline__ uint32_t smem_u32(const void* p) {
    uint32_t a;
    asm("{ .reg .u64 t; cvta.to.shared.u64 t, %1; cvt.u32.u64 %0, t; }" : "=r"(a) : "l"(p));
    return a;
}
#define SWZ(off) ((off) ^ (((off) >> 3) & 0x70))

#define CPA16(d, s) asm volatile("cp.async.cg.shared.global [%0], [%1], 16;" :: "r"(d), "l"(s))
#define CPA_COMMIT() asm volatile("cp.async.commit_group;" ::: "memory")
#define CPA_WAIT0()  asm volatile("cp.async.wait_group 0;" ::: "memory")

__device__ __forceinline__ void ldsm_x4(uint32_t& r0, uint32_t& r1, uint32_t& r2, uint32_t& r3,
                                        uint32_t a) {
    asm volatile("ldmatrix.sync.aligned.m8n8.x4.shared.b16 {%0,%1,%2,%3}, [%4];"
                 : "=r"(r0), "=r"(r1), "=r"(r2), "=r"(r3) : "r"(a));
}
__device__ __forceinline__ void mma16816(float* d, const uint32_t* a, const uint32_t* b) {
    asm volatile("mma.sync.aligned.m16n8k16.row.col.f32.f16.f16.f32 "
                 "{%0,%1,%2,%3}, {%4,%5,%6,%7}, {%8,%9}, {%0,%1,%2,%3};"
                 : "+f"(d[0]), "+f"(d[1]), "+f"(d[2]), "+f"(d[3])
                 : "r"(a[0]), "r"(a[1]), "r"(a[2]), "r"(a[3]), "r"(b[0]), "r"(b[1]));
}

// ---------------- prep: 16 rows/CTA x 16 threads/row, grid 512 ----------------
__global__ void __launch_bounds__(256) prep_kernel(const float* __restrict__ xa,
                                                   const float* __restrict__ xb,
                                                   const float* __restrict__ Wm,
                                                   const float* __restrict__ bv,
                                                   const float* __restrict__ av, int use_gx) {
    __shared__ float Ws[DH * DH];
    __shared__ float as_[2 * DH];
    __shared__ float bs[DH];
    int t = threadIdx.x;
    for (int k = t; k < DH * DH; k += 256) Ws[k] = Wm[k];
    if (t < 2 * DH) as_[t] = av[t];
    if (t < DH) bs[t] = bv[t];
    __syncthreads();

    int row_loc = t >> 4, q = t & 15;
    int row = blockIdx.x * 16 + row_loc;

    float x[DH];
    if (use_gx) {
        const float* p0 = g_part + (size_t)row * DH;
        const float* p1 = g_part + (size_t)NN * DH + (size_t)row * DH;
        float inv = 1.0f / (g_den[row] + g_den[NN + row]);
#pragma unroll
        for (int j = 0; j < 16; j++) {
            float4 v0 = ((const float4*)p0)[j];
            float4 v1 = ((const float4*)p1)[j];
            x[4 * j]     = fmaxf((v0.x + v1.x) * inv, 0.f);
            x[4 * j + 1] = fmaxf((v0.y + v1.y) * inv, 0.f);
            x[4 * j + 2] = fmaxf((v0.z + v1.z) * inv, 0.f);
            x[4 * j + 3] = fmaxf((v0.w + v1.w) * inv, 0.f);
        }
    } else {
        const float* xr = row < NN / 2 ? xa + (size_t)row * DH
                                       : xb + (size_t)(row - NN / 2) * DH;
#pragma unroll
        for (int j = 0; j < 16; j++) {
            float4 v = ((const float4*)xr)[j];
            x[4 * j] = v.x; x[4 * j + 1] = v.y; x[4 * j + 2] = v.z; x[4 * j + 3] = v.w;
        }
    }

    float srcv = 0.f, dstv = 0.f;
#pragma unroll
    for (int ii = 0; ii < 4; ii++) {
        int i = q * 4 + ii;
        const float4* w4 = (const float4*)(Ws + i * DH);
        float a0 = 0.f, a1 = 0.f, a2 = 0.f, a3 = 0.f;
#pragma unroll
        for (int p = 0; p < 16; p += 4) {
            float4 w;
            w = w4[p];     a0 = fmaf(x[4*p+3], w.w, fmaf(x[4*p+2], w.z, fmaf(x[4*p+1], w.y, fmaf(x[4*p], w.x, a0))));
            w = w4[p + 1]; a1 = fmaf(x[4*p+7], w.w, fmaf(x[4*p+6], w.z, fmaf(x[4*p+5], w.y, fmaf(x[4*p+4], w.x, a1))));
            w = w4[p + 2]; a2 = fmaf(x[4*p+11], w.w, fmaf(x[4*p+10], w.z, fmaf(x[4*p+9], w.y, fmaf(x[4*p+8], w.x, a2))));
            w = w4[p + 3]; a3 = fmaf(x[4*p+15], w.w, fmaf(x[4*p+14], w.z, fmaf(x[4*p+13], w.y, fmaf(x[4*p+12], w.x, a3))));
        }
        float wh = bs[i] + ((a0 + a1) + (a2 + a3));
        srcv = fmaf(wh, as_[i], srcv);
        dstv = fmaf(wh, as_[DH + i], dstv);
        g_WhT[(size_t)i * NN + row] = __half_as_ushort(__float2half_rn(wh));
    }
    srcv += __shfl_xor_sync(0xffffffffu, srcv, 1);
    srcv += __shfl_xor_sync(0xffffffffu, srcv, 2);
    srcv += __shfl_xor_sync(0xffffffffu, srcv, 4);
    srcv += __shfl_xor_sync(0xffffffffu, srcv, 8);
    dstv += __shfl_xor_sync(0xffffffffu, dstv, 1);
    dstv += __shfl_xor_sync(0xffffffffu, dstv, 2);
    dstv += __shfl_xor_sync(0xffffffffu, dstv, 4);
    dstv += __shfl_xor_sync(0xffffffffu, dstv, 8);
    if (q == 0) {
        __half2 Ah = __float2half2_rn(expf(srcv));
        __half2 Ch = __float2half2_rn(expf(0.2f * srcv));
        g_iAC[row] = make_uint2(*(uint32_t*)&Ah, *(uint32_t*)&Ch);
        g_jB[row] = __half_as_ushort(__float2half_rn(expf(dstv)));
        g_jD[row] = __half_as_ushort(__float2half_rn(expf(0.2f * dstv)));
    }
}

// ---------------- gen 8 j's per thread (half2) ----------------
template<int L0>
__device__ __forceinline__ void gen8(char* smemp, uint32_t wo, uint32_t wdst,
                                     uint32_t A2, uint32_t C2,
                                     const uint4* pBc, const uint4* pDc,
                                     uint32_t bits, const int4* rv,
                                     uint8_t* packdst, float& dsum) {
    __half2 A2h = *(__half2*)&A2, C2h = *(__half2*)&C2;
    uint4 Bq = pBc[0], Dq = pDc[0];
    uint32_t Bw[4] = {Bq.x, Bq.y, Bq.z, Bq.w};
    uint32_t Dw[4] = {Dq.x, Dq.y, Dq.z, Dq.w};
    uint32_t wv[4];
    uint32_t packbits = 0;
#pragma unroll
    for (int p = 0; p < 4; p++) {
        __half2 ab = __hmul2(A2h, *(__half2*)&Bw[p]);
        __half2 cd = __hmul2(C2h, *(__half2*)&Dw[p]);
        __half2 w = __hmax2(ab, cd);      // exp(leaky_relu(src+dst)) — exp monotone
        uint32_t m;
        if (L0) {
            int4 a4 = rv[p >> 1];
            int v0 = (p & 1) ? a4.z : a4.x;
            int v1 = (p & 1) ? a4.w : a4.y;
            m = (v0 != 0 ? 0x0000FFFFu : 0u) | (v1 != 0 ? 0xFFFF0000u : 0u);
            packbits |= (v0 != 0 ? 1u : 0u) << (2 * p);
            packbits |= (v1 != 0 ? 1u : 0u) << (2 * p + 1);
        } else {
            uint32_t e = (bits >> (2 * p)) & 3u;
            m = ((e * 0x8001u) & 0x10001u) * 0xFFFFu;
        }
        wv[p] = (*(uint32_t*)&w) & m;
    }
    __half2 s01 = __hadd2(*(__half2*)&wv[0], *(__half2*)&wv[1]);
    __half2 s23 = __hadd2(*(__half2*)&wv[2], *(__half2*)&wv[3]);
    float2 fs = __half22float2(__hadd2(s01, s23));
    dsum += fs.x + fs.y;

    *(uint4*)(smemp + wo + wdst) = make_uint4(wv[0], wv[1], wv[2], wv[3]);
    if (L0) *packdst = (uint8_t)packbits;
}

// ---------------- attn: HMMA flash-GAT, 32 x 4096 per CTA, grid 512 ----------------
// L0=1: reads raw adj (int4 register prefetch), emits packed bits.
template<int L0>
__global__ void __launch_bounds__(TPB, 3) attn_mma(const int* __restrict__ adj) {
    extern __shared__ char smem[];
    uint32_t sb = smem_u32(smem);
    int t = threadIdx.x, wid = t >> 5, lane = t & 31;
    int tile = blockIdx.x >> 1, ks = blockIdx.x & 1;
    int i0 = tile * TILE_I, jbase = ks * KHALF;

    // ---- gen mapping: 32 rows x 8 threads/row; 8 j's per thread ----
    int i_loc = t >> 3, jq8 = t & 7;
    int irow = i0 + i_loc;
    uint2 ac = g_iAC[irow];
    uint32_t wdst = SWZ((uint32_t)(i_loc * 128 + jq8 * 16));
    const uint4* pB = (const uint4*)(g_jB + jbase) + jq8;   // +8 per chunk
    const uint4* pD = (const uint4*)(g_jD + jbase) + jq8;
    uint8_t* pPackB = g_adjpB + (size_t)irow * 1024 + (jbase >> 3) + jq8;  // +8 per chunk
    const int4* pAdj = (const int4*)(adj + (size_t)irow * NN + jbase) + jq8 * 2;  // +16 per chunk
    float dsum = 0.f;

    // ---- B staging (cp.async): 512 16B segs = 2/thread ----
    int s0 = t, s1 = t + 256;
    uint32_t bd0 = SWZ((uint32_t)((s0 >> 3) * 128 + (s0 & 7) * 16));
    uint32_t bd1 = SWZ((uint32_t)((s1 >> 3) * 128 + (s1 & 7) * 16));
    const unsigned short* bs0p = g_WhT + (size_t)(s0 >> 3) * NN + jbase + (s0 & 7) * 8;
    const unsigned short* bs1p = g_WhT + (size_t)(s1 >> 3) * NN + jbase + (s1 & 7) * 8;

    // ---- GEMM mapping: 8 warps = 2 M-tiles(16) x 4 N-tiles(16) ----
    int wm = wid & 1, wn = wid >> 1;
    int lr = lane & 7, lsel = lane >> 3;
    float acc[2][4];
#pragma unroll
    for (int n = 0; n < 2; n++)
#pragma unroll
        for (int p = 0; p < 4; p++) acc[n][p] = 0.f;

    // ---- prefetch + stage chunk 0 ----
    uint32_t bits = 0;
    int4 rv[2];
    if (L0) { rv[0] = pAdj[0]; rv[1] = pAdj[1]; }
    else bits = pPackB[0];
    CPA16(sb + BOFF0 + bd0, bs0p);
    CPA16(sb + BOFF0 + bd1, bs1p);
    CPA_COMMIT();
    gen8<L0>(smem, WOFF0, wdst, ac.x, ac.y, pB, pD, bits, rv, pPackB, dsum);
    if (L0) { rv[0] = pAdj[16]; rv[1] = pAdj[17]; }
    else bits = pPackB[8];
    CPA_WAIT0();
    __syncthreads();

    for (int c = 0; c < NCH; c++) {
        int buf = c & 1;
        if (c + 1 < NCH) {
            int nb = buf ^ 1;
            uint32_t bo = nb ? BOFF1 : BOFF0, wo = nb ? WOFF1 : WOFF0;
            CPA16(sb + bo + bd0, bs0p + (c + 1) * 64);
            CPA16(sb + bo + bd1, bs1p + (c + 1) * 64);
            CPA_COMMIT();
            gen8<L0>(smem, wo, wdst, ac.x, ac.y,
                     pB + (size_t)(c + 1) * 8, pD + (size_t)(c + 1) * 8,
                     bits, rv, pPackB + (c + 1) * 8, dsum);
            if (c + 2 < NCH) {
                if (L0) { rv[0] = pAdj[(c + 2) * 16]; rv[1] = pAdj[(c + 2) * 16 + 1]; }
                else bits = pPackB[(c + 2) * 8];
            }
        }

        // ---- GEMM on chunk c ----
        uint32_t wbase = sb + (buf ? WOFF1 : WOFF0);
        uint32_t bbase = sb + (buf ? BOFF1 : BOFF0);
#pragma unroll
        for (int k = 0; k < 4; k++) {
            uint32_t af[4], bf[4];
            uint32_t a_adr = wbase + SWZ((uint32_t)((wm * 16 + lr + (lsel & 1) * 8) * 128 + ((lsel >> 1) * 8 + k * 16) * 2));
            ldsm_x4(af[0], af[1], af[2], af[3], a_adr);
            uint32_t b_adr = bbase + SWZ((uint32_t)((wn * 16 + lr + (lsel >> 1) * 8) * 128 + ((lsel & 1) * 8 + k * 16) * 2));
            ldsm_x4(bf[0], bf[1], bf[2], bf[3], b_adr);
            mma16816(acc[0], af, bf + 0);
            mma16816(acc[1], af, bf + 2);
        }
        CPA_WAIT0();
        __syncthreads();
    }

    // ---- denominator: reduce over the 8 gen threads of each row ----
    dsum += __shfl_xor_sync(0xffffffffu, dsum, 1);
    dsum += __shfl_xor_sync(0xffffffffu, dsum, 2);
    dsum += __shfl_xor_sync(0xffffffffu, dsum, 4);
    if (jq8 == 0) g_den[(size_t)ks * NN + irow] = dsum;

    // ---- epilogue: write partial numerators ----
    int row0 = i0 + wm * 16 + (lane >> 2);
    float* base = g_part + (size_t)ks * NN * DH;
#pragma unroll
    for (int nt = 0; nt < 2; nt++) {
        int col = wn * 16 + nt * 8 + (lane & 3) * 2;
        *(float2*)(base + (size_t)row0 * DH + col) = make_float2(acc[nt][0], acc[nt][1]);
        *(float2*)(base + (size_t)(row0 + 8) * DH + col) = make_float2(acc[nt][2], acc[nt][3]);
    }
}

// ---------------- final: fused combine + out = x @ out_w^T + out_b ----------------
// 32 rows/CTA x 8 threads/row, grid 256.
__global__ void __launch_bounds__(256) final_kernel(const float* __restrict__ Wm,
                                                    const float* __restrict__ bv,
                                                    float* __restrict__ out) {
    __shared__ float Ws[DH * DH];
    __shared__ float bs[DH];
    int t = threadIdx.x;
    for (int k = t; k < DH * DH; k += 256) Ws[k] = Wm[k];
    if (t < DH) bs[t] = bv[t];
    __syncthreads();

    int row_loc = t >> 3, q = t & 7;
    int row = blockIdx.x * 32 + row_loc;

    const float* p0 = g_part + (size_t)row * DH;
    const float* p1 = g_part + (size_t)NN * DH + (size_t)row * DH;
    float inv = 1.0f / (g_den[row] + g_den[NN + row]);
    float x[DH];
#pragma unroll
    for (int j = 0; j < 16; j++) {
        float4 v0 = ((const float4*)p0)[j];
        float4 v1 = ((const float4*)p1)[j];
        x[4 * j]     = fmaxf((v0.x + v1.x) * inv, 0.f);
        x[4 * j + 1] = fmaxf((v0.y + v1.y) * inv, 0.f);
        x[4 * j + 2] = fmaxf((v0.z + v1.z) * inv, 0.f);
        x[4 * j + 3] = fmaxf((v0.w + v1.w) * inv, 0.f);
    }

    float res[8];
#pragma unroll
    for (int ii = 0; ii < 8; ii++) {
        int i = q * 8 + ii;
        const float4* w4 = (const float4*)(Ws + i * DH);
        float a0 = 0.f, a1 = 0.f, a2 = 0.f, a3 = 0.f;
#pragma unroll
        for (int p = 0; p < 16; p += 4) {
            float4 w;
            w = w4[p];     a0 = fmaf(x[4*p+3], w.w, fmaf(x[4*p+2], w.z, fmaf(x[4*p+1], w.y, fmaf(x[4*p], w.x, a0))));
            w = w4[p + 1]; a1 = fmaf(x[4*p+7], w.w, fmaf(x[4*p+6], w.z, fmaf(x[4*p+5], w.y, fmaf(x[4*p+4], w.x, a1))));
            w = w4[p + 2]; a2 = fmaf(x[4*p+11], w.w, fmaf(x[4*p+10], w.z, fmaf(x[4*p+9], w.y, fmaf(x[4*p+8], w.x, a2))));
            w = w4[p + 3]; a3 = fmaf(x[4*p+15], w.w, fmaf(x[4*p+14], w.z, fmaf(x[4*p+13], w.y, fmaf(x[4*p+12], w.x, a3))));
        }
        res[ii] = bs[i] + ((a0 + a1) + (a2 + a3));
    }
    float* orow = out + (size_t)row * DH + q * 8;
    ((float4*)orow)[0] = make_float4(res[0], res[1], res[2], res[3]);
    ((float4*)orow)[1] = make_float4(res[4], res[5], res[6], res[7]);
}

// ---------------- launch ----------------
extern "C" void kernel_launch(void* const* d_in, const int* in_sizes, int n_in,
                              void* d_out, int out_size) {
    const int*   adj  = (const int*)d_in[0];
    const float* user = (const float*)d_in[1];
    const float* item = (const float*)d_in[2];
    const float* W0   = (const float*)d_in[3];
    const float* b0   = (const float*)d_in[4];
    const float* a0   = (const float*)d_in[5];
    const float* W1   = (const float*)d_in[6];
    const float* b1   = (const float*)d_in[7];
    const float* a1   = (const float*)d_in[8];
    const float* ow   = (const float*)d_in[9];
    const float* ob   = (const float*)d_in[10];

    cudaFuncSetAttribute(attn_mma<1>, cudaFuncAttributeMaxDynamicSharedMemorySize, SMEM_BYTES);
    cudaFuncSetAttribute(attn_mma<0>, cudaFuncAttributeMaxDynamicSharedMemorySize, SMEM_BYTES);

    prep_kernel<<<NN / 16, 256>>>(user, item, W0, b0, a0, 0);
    attn_mma<1><<<(NN / TILE_I) * KSPLIT, TPB, SMEM_BYTES>>>(adj);   // fused: raw adj + packs bits
    prep_kernel<<<NN / 16, 256>>>(nullptr, nullptr, W1, b1, a1, 1);  // fused combine
    attn_mma<0><<<(NN / TILE_I) * KSPLIT, TPB, SMEM_BYTES>>>(adj);   // reads packed bits
    final_kernel<<<NN / 32, 256>>>(ow, ob, (float*)d_out);           // fused combine
}

// round 12
// speedup vs baseline: 1.9621x; 1.9621x over previous
#include <cuda_runtime.h>
#include <cuda_fp16.h>
#include <stdint.h>

#define NN 8192
#define DH 64
#define NCOL 80            // 64 cols + denom col(64) + 15 zero pad
#define KC 64              // j's per chunk
#define KSPLIT 2
#define KHALF (NN / KSPLIT)
#define NCH (KHALF / KC)   // 64 chunks
#define TPB 256
#define TILE_I 64
// smem: W tile 64x64 fp16 (8KB) x2, B tile 80x64 fp16 (10KB) x2
#define WOFF0 0
#define WOFF1 8192
#define BOFF0 16384
#define BOFF1 26624
#define SMEM_BYTES 36864

// ---------------- device scratch ----------------
__device__ unsigned short g_adjp[NN * 512];    // packed adjacency bits (8MB)
__device__ unsigned short g_WhT[NCOL * NN];    // Wh^T fp16 [80][8192]; row64=1, 65..79=0
__device__ uint2 g_iAC[NN];                    // {half2(exp(src)), half2(exp(.2src))}
__device__ unsigned short g_jB[NN];            // half exp(dst)
__device__ unsigned short g_jD[NN];            // half exp(.2 dst)
__device__ float g_part[KSPLIT * NN * NCOL];   // K-split partials (denom in col 64)

// ---------------- helpers ----------------
__device__ __forceinline__ uint32_t smem_u32(const void* p) {
    uint32_t a;
    asm("{ .reg .u64 t; cvta.to.shared.u64 t, %1; cvt.u32.u64 %0, t; }" : "=r"(a) : "l"(p));
    return a;
}
#define SWZ(off) ((off) ^ (((off) >> 3) & 0x70))

#define CPA16(d, s) asm volatile("cp.async.cg.shared.global [%0], [%1], 16;" :: "r"(d), "l"(s))
#define CPA_COMMIT() asm volatile("cp.async.commit_group;" ::: "memory")
#define CPA_WAIT0()  asm volatile("cp.async.wait_group 0;" ::: "memory")

__device__ __forceinline__ void ldsm_x4(uint32_t& r0, uint32_t& r1, uint32_t& r2, uint32_t& r3,
                                        uint32_t a) {
    asm volatile("ldmatrix.sync.aligned.m8n8.x4.shared.b16 {%0,%1,%2,%3}, [%4];"
                 : "=r"(r0), "=r"(r1), "=r"(r2), "=r"(r3) : "r"(a));
}
__device__ __forceinline__ void ldsm_x2(uint32_t& r0, uint32_t& r1, uint32_t a) {
    asm volatile("ldmatrix.sync.aligned.m8n8.x2.shared.b16 {%0,%1}, [%2];"
                 : "=r"(r0), "=r"(r1) : "r"(a));
}
__device__ __forceinline__ void mma16816(float* d, const uint32_t* a, const uint32_t* b) {
    asm volatile("mma.sync.aligned.m16n8k16.row.col.f32.f16.f16.f32 "
                 "{%0,%1,%2,%3}, {%4,%5,%6,%7}, {%8,%9}, {%0,%1,%2,%3};"
                 : "+f"(d[0]), "+f"(d[1]), "+f"(d[2]), "+f"(d[3])
                 : "r"(a[0]), "r"(a[1]), "r"(a[2]), "r"(a[3]), "r"(b[0]), "r"(b[1]));
}

// ---------------- prep: Wh^T fp16, per-node exp factors (fused combine for layer 1) -------
__global__ void __launch_bounds__(64) prep_kernel(const float* __restrict__ xa,
                                                  const float* __restrict__ xb,
                                                  const float* __restrict__ Wm,
                                                  const float* __restrict__ bv,
                                                  const float* __restrict__ av, int use_gx) {
    __shared__ float Ws[DH * DH];
    __shared__ float as_[2 * DH];
    __shared__ float bs[DH];
    int t = threadIdx.x;
    for (int k = t; k < DH * DH; k += 64) Ws[k] = Wm[k];
    if (t < DH) { as_[t] = av[t]; as_[DH + t] = av[DH + t]; bs[t] = bv[t]; }
    __syncthreads();

    int row = blockIdx.x * 64 + t;
    float x[DH];
    if (use_gx) {
        // fused combine: normalize K-split partials + relu
        const float* p0 = g_part + (size_t)row * NCOL;
        const float* p1 = g_part + (size_t)NN * NCOL + (size_t)row * NCOL;
        float inv = 1.0f / (p0[64] + p1[64]);
#pragma unroll
        for (int q = 0; q < 16; q++) {
            float4 v0 = ((const float4*)p0)[q];
            float4 v1 = ((const float4*)p1)[q];
            x[4 * q]     = fmaxf((v0.x + v1.x) * inv, 0.f);
            x[4 * q + 1] = fmaxf((v0.y + v1.y) * inv, 0.f);
            x[4 * q + 2] = fmaxf((v0.z + v1.z) * inv, 0.f);
            x[4 * q + 3] = fmaxf((v0.w + v1.w) * inv, 0.f);
        }
    } else {
        const float* xr = row < NN / 2 ? xa + (size_t)row * DH
                                       : xb + (size_t)(row - NN / 2) * DH;
#pragma unroll
        for (int q = 0; q < 16; q++) {
            float4 v = ((const float4*)xr)[q];
            x[4 * q] = v.x; x[4 * q + 1] = v.y; x[4 * q + 2] = v.z; x[4 * q + 3] = v.w;
        }
    }

    float srcv = 0.f, dstv = 0.f;
    for (int i = 0; i < DH; i++) {
        const float4* w4 = (const float4*)(Ws + i * DH);
        float a0 = 0.f, a1 = 0.f, a2 = 0.f, a3 = 0.f;
#pragma unroll
        for (int q = 0; q < 16; q += 4) {
            float4 w;
            w = w4[q];     a0 = fmaf(x[4*q+3], w.w, fmaf(x[4*q+2], w.z, fmaf(x[4*q+1], w.y, fmaf(x[4*q], w.x, a0))));
            w = w4[q + 1]; a1 = fmaf(x[4*q+7], w.w, fmaf(x[4*q+6], w.z, fmaf(x[4*q+5], w.y, fmaf(x[4*q+4], w.x, a1))));
            w = w4[q + 2]; a2 = fmaf(x[4*q+11], w.w, fmaf(x[4*q+10], w.z, fmaf(x[4*q+9], w.y, fmaf(x[4*q+8], w.x, a2))));
            w = w4[q + 3]; a3 = fmaf(x[4*q+15], w.w, fmaf(x[4*q+14], w.z, fmaf(x[4*q+13], w.y, fmaf(x[4*q+12], w.x, a3))));
        }
        float wh = bs[i] + ((a0 + a1) + (a2 + a3));
        srcv = fmaf(wh, as_[i], srcv);
        dstv = fmaf(wh, as_[DH + i], dstv);
        g_WhT[(size_t)i * NN + row] = __half_as_ushort(__float2half_rn(wh));
    }
    g_WhT[(size_t)64 * NN + row] = __half_as_ushort(__float2half_rn(1.0f));
#pragma unroll
    for (int d = 65; d < NCOL; d++) g_WhT[(size_t)d * NN + row] = 0;

    __half2 Ah = __float2half2_rn(expf(srcv));
    __half2 Ch = __float2half2_rn(expf(0.2f * srcv));
    g_iAC[row] = make_uint2(*(uint32_t*)&Ah, *(uint32_t*)&Ch);
    g_jB[row] = __half_as_ushort(__float2half_rn(expf(dstv)));
    g_jD[row] = __half_as_ushort(__float2half_rn(expf(0.2f * dstv)));
}

// ---------------- weight-tile generation (half2, no sign test) ----------------
template<int L0>
__device__ __forceinline__ void gen_store(char* smemp, uint32_t wo, uint32_t wdst0, uint32_t wdst1,
                                          uint32_t A2, uint32_t C2,
                                          const uint4& B0, const uint4& B1,
                                          const uint4& D0, const uint4& D1,
                                          uint32_t bits_in, const int* vi,
                                          unsigned short* packdst) {
    uint32_t Bw[8] = {B0.x, B0.y, B0.z, B0.w, B1.x, B1.y, B1.z, B1.w};
    uint32_t Dw[8] = {D0.x, D0.y, D0.z, D0.w, D1.x, D1.y, D1.z, D1.w};
    uint32_t wv[8];
    uint32_t packbits = 0;
    __half2 A2h = *(__half2*)&A2, C2h = *(__half2*)&C2;
#pragma unroll
    for (int p = 0; p < 8; p++) {
        __half2 ab = __hmul2(A2h, *(__half2*)&Bw[p]);
        __half2 cd = __hmul2(C2h, *(__half2*)&Dw[p]);
        __half2 w = __hmax2(ab, cd);      // = exp(leaky_relu(src+dst)) — exp monotone
        uint32_t m;
        if (L0) {
            int v0 = vi[2 * p], v1 = vi[2 * p + 1];
            m = (v0 != 0 ? 0x0000FFFFu : 0u) | (v1 != 0 ? 0xFFFF0000u : 0u);
            packbits |= (v0 != 0 ? 1u : 0u) << (2 * p);
            packbits |= (v1 != 0 ? 1u : 0u) << (2 * p + 1);
        } else {
            uint32_t e = (bits_in >> (2 * p)) & 3u;
            uint32_t xm = (e * 0x8001u) & 0x10001u;
            m = xm * 0xFFFFu;             // 0xFFFF per set bit, per half
        }
        wv[p] = (*(uint32_t*)&w) & m;
    }
    *(uint4*)(smemp + wo + wdst0) = make_uint4(wv[0], wv[1], wv[2], wv[3]);
    *(uint4*)(smemp + wo + wdst1) = make_uint4(wv[4], wv[5], wv[6], wv[7]);
    if (L0) *packdst = (unsigned short)packbits;
}

// ---------------- attn: HMMA flash-GAT, 64x4096 per CTA ----------------
template<int L0>
__global__ void __launch_bounds__(TPB, 2) attn_mma(const int* __restrict__ adj) {
    extern __shared__ char smem[];
    uint32_t sb = smem_u32(smem);
    int t = threadIdx.x, wid = t >> 5, lane = t & 31;
    int tile = blockIdx.x >> 1, ks = blockIdx.x & 1;
    int i0 = tile * TILE_I, jbase = ks * KHALF;

    // ---- gen mapping: thread -> row i_loc, 16 j's ----
    int i_loc = t >> 2, jq16 = t & 3;
    int irow = i0 + i_loc;
    uint2 ac = g_iAC[irow];
    uint32_t wdst0 = SWZ((uint32_t)(i_loc * 128 + jq16 * 32));
    uint32_t wdst1 = SWZ((uint32_t)(i_loc * 128 + jq16 * 32 + 16));
    const uint4* pB = (const uint4*)(g_jB + jbase) + jq16 * 2;
    const uint4* pD = (const uint4*)(g_jD + jbase) + jq16 * 2;
    const int4* pAdj = (const int4*)(adj + (size_t)irow * NN + jbase) + jq16 * 4;
    unsigned short* pPack = g_adjp + (size_t)irow * 512 + (jbase >> 4) + jq16;

    // ---- B staging mapping (cp.async): 640 16B segs ----
    int s0 = t, s1 = t + 256, s2 = t + 512;
    uint32_t bd0 = SWZ((uint32_t)((s0 >> 3) * 128 + (s0 & 7) * 16));
    uint32_t bd1 = SWZ((uint32_t)((s1 >> 3) * 128 + (s1 & 7) * 16));
    uint32_t bd2 = SWZ((uint32_t)((s2 >> 3) * 128 + (s2 & 7) * 16));
    const unsigned short* bs0p = g_WhT + (size_t)(s0 >> 3) * NN + jbase + (s0 & 7) * 8;
    const unsigned short* bs1p = g_WhT + (size_t)(s1 >> 3) * NN + jbase + (s1 & 7) * 8;
    const unsigned short* bs2p = g_WhT + (size_t)(s2 >> 3) * NN + jbase + (s2 & 7) * 8;

    // ---- GEMM mapping: 8 warps = 4 M-tiles x 2 N-halves ----
    int wm = wid & 3, wn = wid >> 2;
    int lr = lane & 7, lsel = lane >> 3;
    float acc[5][4];
#pragma unroll
    for (int n = 0; n < 5; n++)
#pragma unroll
        for (int q = 0; q < 4; q++) acc[n][q] = 0.f;

    // ---- prefetch regs for chunk 0 ----
    uint4 Bq0 = pB[0], Bq1 = pB[1], Dq0 = pD[0], Dq1 = pD[1];
    uint32_t bits = 0;
    int4 rv[4];
    if (L0) {
        rv[0] = __ldcs(pAdj + 0); rv[1] = __ldcs(pAdj + 1);
        rv[2] = __ldcs(pAdj + 2); rv[3] = __ldcs(pAdj + 3);
    } else bits = pPack[0];

    // ---- stage chunk 0 ----
    CPA16(sb + BOFF0 + bd0, bs0p);
    CPA16(sb + BOFF0 + bd1, bs1p);
    if (t < 128) CPA16(sb + BOFF0 + bd2, bs2p);
    CPA_COMMIT();
    gen_store<L0>(smem, WOFF0, wdst0, wdst1, ac.x, ac.y, Bq0, Bq1, Dq0, Dq1,
                  bits, (const int*)rv, pPack);
    // prefetch chunk 1
    Bq0 = pB[8]; Bq1 = pB[9]; Dq0 = pD[8]; Dq1 = pD[9];
    if (L0) {
        rv[0] = __ldcs(pAdj + 16); rv[1] = __ldcs(pAdj + 17);
        rv[2] = __ldcs(pAdj + 18); rv[3] = __ldcs(pAdj + 19);
    } else bits = pPack[4];
    CPA_WAIT0();
    __syncthreads();

    for (int c = 0; c < NCH; c++) {
        int buf = c & 1;
        if (c + 1 < NCH) {
            int nb = buf ^ 1;
            uint32_t bo = nb ? BOFF1 : BOFF0, wo = nb ? WOFF1 : WOFF0;
            CPA16(sb + bo + bd0, bs0p + (c + 1) * 64);
            CPA16(sb + bo + bd1, bs1p + (c + 1) * 64);
            if (t < 128) CPA16(sb + bo + bd2, bs2p + (c + 1) * 64);
            CPA_COMMIT();
            gen_store<L0>(smem, wo, wdst0, wdst1, ac.x, ac.y, Bq0, Bq1, Dq0, Dq1,
                          bits, (const int*)rv, pPack + (c + 1) * 4);
            if (c + 2 < NCH) {
                Bq0 = pB[(c + 2) * 8]; Bq1 = pB[(c + 2) * 8 + 1];
                Dq0 = pD[(c + 2) * 8]; Dq1 = pD[(c + 2) * 8 + 1];
                if (L0) {
                    rv[0] = __ldcs(pAdj + (c + 2) * 16);     rv[1] = __ldcs(pAdj + (c + 2) * 16 + 1);
                    rv[2] = __ldcs(pAdj + (c + 2) * 16 + 2); rv[3] = __ldcs(pAdj + (c + 2) * 16 + 3);
                } else bits = pPack[(c + 2) * 4];
            }
        }

        // ---- GEMM on chunk c ----
        uint32_t wbase = sb + (buf ? WOFF1 : WOFF0);
        uint32_t bbase = sb + (buf ? BOFF1 : BOFF0);
#pragma unroll
        for (int k = 0; k < 4; k++) {
            uint32_t af[4], bf[10];
            uint32_t a_adr = wbase + SWZ((uint32_t)((wm * 16 + lr + (lsel & 1) * 8) * 128 + ((lsel >> 1) * 8 + k * 16) * 2));
            ldsm_x4(af[0], af[1], af[2], af[3], a_adr);
#pragma unroll
            for (int p = 0; p < 2; p++) {
                uint32_t b_adr = bbase + SWZ((uint32_t)((wn * 40 + p * 16 + lr + (lsel >> 1) * 8) * 128 + ((lsel & 1) * 8 + k * 16) * 2));
                ldsm_x4(bf[p * 4 + 0], bf[p * 4 + 1], bf[p * 4 + 2], bf[p * 4 + 3], b_adr);
            }
            {
                uint32_t b_adr = bbase + SWZ((uint32_t)((wn * 40 + 32 + lr) * 128 + ((((lane >> 3) & 1) * 8) + k * 16) * 2));
                ldsm_x2(bf[8], bf[9], b_adr);
            }
            mma16816(acc[0], af, bf + 0);
            mma16816(acc[1], af, bf + 2);
            mma16816(acc[2], af, bf + 4);
            mma16816(acc[3], af, bf + 6);
            mma16816(acc[4], af, bf + 8);
        }
        CPA_WAIT0();
        __syncthreads();
    }

    // ---- epilogue: write partials ----
    int row0 = i0 + wm * 16 + (lane >> 2);
    float* base = g_part + ((size_t)ks * NN) * NCOL;
#pragma unroll
    for (int nt = 0; nt < 5; nt++) {
        int col = wn * 40 + nt * 8 + (lane & 3) * 2;
        *(float2*)(base + (size_t)row0 * NCOL + col) = make_float2(acc[nt][0], acc[nt][1]);
        *(float2*)(base + (size_t)(row0 + 8) * NCOL + col) = make_float2(acc[nt][2], acc[nt][3]);
    }
}

// ---------------- final: fused combine + out = x @ out_w^T + out_b ----------------
__global__ void __launch_bounds__(64) final_kernel(const float* __restrict__ Wm,
                                                   const float* __restrict__ bv,
                                                   float* __restrict__ out) {
    __shared__ float Ws[DH * DH];
    __shared__ float bs[DH];
    int t = threadIdx.x;
    for (int k = t; k < DH * DH; k += 64) Ws[k] = Wm[k];
    if (t < DH) bs[t] = bv[t];
    __syncthreads();

    int row = blockIdx.x * 64 + t;
    const float* p0 = g_part + (size_t)row * NCOL;
    const float* p1 = g_part + (size_t)NN * NCOL + (size_t)row * NCOL;
    float inv = 1.0f / (p0[64] + p1[64]);
    float x[DH];
#pragma unroll
    for (int q = 0; q < 16; q++) {
        float4 v0 = ((const float4*)p0)[q];
        float4 v1 = ((const float4*)p1)[q];
        x[4 * q]     = fmaxf((v0.x + v1.x) * inv, 0.f);
        x[4 * q + 1] = fmaxf((v0.y + v1.y) * inv, 0.f);
        x[4 * q + 2] = fmaxf((v0.z + v1.z) * inv, 0.f);
        x[4 * q + 3] = fmaxf((v0.w + v1.w) * inv, 0.f);
    }

    float* orow = out + (size_t)row * DH;
    for (int i = 0; i < DH; i += 4) {
        float4 res;
#pragma unroll
        for (int u = 0; u < 4; u++) {
            const float4* w4 = (const float4*)(Ws + (i + u) * DH);
            float a0 = 0.f, a1 = 0.f, a2 = 0.f, a3 = 0.f;
#pragma unroll
            for (int q = 0; q < 16; q += 4) {
                float4 w;
                w = w4[q];     a0 = fmaf(x[4*q+3], w.w, fmaf(x[4*q+2], w.z, fmaf(x[4*q+1], w.y, fmaf(x[4*q], w.x, a0))));
                w = w4[q + 1]; a1 = fmaf(x[4*q+7], w.w, fmaf(x[4*q+6], w.z, fmaf(x[4*q+5], w.y, fmaf(x[4*q+4], w.x, a1))));
                w = w4[q + 2]; a2 = fmaf(x[4*q+11], w.w, fmaf(x[4*q+10], w.z, fmaf(x[4*q+9], w.y, fmaf(x[4*q+8], w.x, a2))));
                w = w4[q + 3]; a3 = fmaf(x[4*q+15], w.w, fmaf(x[4*q+14], w.z, fmaf(x[4*q+13], w.y, fmaf(x[4*q+12], w.x, a3))));
            }
            ((float*)&res)[u] = bs[i + u] + ((a0 + a1) + (a2 + a3));
        }
        ((float4*)orow)[i >> 2] = res;
    }
}

// ---------------- launch ----------------
extern "C" void kernel_launch(void* const* d_in, const int* in_sizes, int n_in,
                              void* d_out, int out_size) {
    const int*   adj  = (const int*)d_in[0];
    const float* user = (const float*)d_in[1];
    const float* item = (const float*)d_in[2];
    const float* W0   = (const float*)d_in[3];
    const float* b0   = (const float*)d_in[4];
    const float* a0   = (const float*)d_in[5];
    const float* W1   = (const float*)d_in[6];
    const float* b1   = (const float*)d_in[7];
    const float* a1   = (const float*)d_in[8];
    const float* ow   = (const float*)d_in[9];
    const float* ob   = (const float*)d_in[10];

    cudaFuncSetAttribute(attn_mma<1>, cudaFuncAttributeMaxDynamicSharedMemorySize, SMEM_BYTES);
    cudaFuncSetAttribute(attn_mma<0>, cudaFuncAttributeMaxDynamicSharedMemorySize, SMEM_BYTES);

    prep_kernel<<<NN / 64, 64>>>(user, item, W0, b0, a0, 0);
    attn_mma<1><<<(NN / TILE_I) * KSPLIT, TPB, SMEM_BYTES>>>(adj);   // fused: packs adj bits
    prep_kernel<<<NN / 64, 64>>>(nullptr, nullptr, W1, b1, a1, 1);   // fused combine
    attn_mma<0><<<(NN / TILE_I) * KSPLIT, TPB, SMEM_BYTES>>>(adj);   // reads packed bits
    final_kernel<<<NN / 64, 64>>>(ow, ob, (float*)d_out);            // fused combine
}

// round 13
// speedup vs baseline: 2.0526x; 1.0461x over previous
#include <cuda_runtime.h>
#include <cuda_fp16.h>
#include <stdint.h>

#define NN 8192
#define DH 64
#define KC 64              // j's per chunk
#define KSPLIT 2
#define KHALF (NN / KSPLIT)
#define NCH (KHALF / KC)   // 64 chunks
#define TPB 256
#define TILE_I 64
// smem: W tile 64x64 fp16 (8KB) x2, B tile 64x64 fp16 (8KB) x2
#define WOFF0 0
#define WOFF1 8192
#define BOFF0 16384
#define BOFF1 24576
#define SMEM_BYTES 32768

// ---------------- device scratch ----------------
__device__ unsigned short g_adjp[NN * 512];    // packed adjacency bits (8MB)
__device__ unsigned short g_WhT[DH * NN];      // Wh^T fp16 [64][8192]
__device__ uint2 g_iAC[NN];                    // {half2(exp(src)), half2(exp(.2src))}
__device__ unsigned short g_jB[NN];            // half exp(dst)
__device__ unsigned short g_jD[NN];            // half exp(.2 dst)
__device__ float g_part[KSPLIT * NN * DH];     // K-split partial numerators
__device__ float g_den[KSPLIT * NN];           // K-split partial denominators

// ---------------- helpers ----------------
__device__ __forceinline__ uint32_t smem_u32(const void* p) {
    uint32_t a;
    asm("{ .reg .u64 t; cvta.to.shared.u64 t, %1; cvt.u32.u64 %0, t; }" : "=r"(a) : "l"(p));
    return a;
}
#define SWZ(off) ((off) ^ (((off) >> 3) & 0x70))

#define CPA16(d, s) asm volatile("cp.async.cg.shared.global [%0], [%1], 16;" :: "r"(d), "l"(s))
#define CPA_COMMIT() asm volatile("cp.async.commit_group;" ::: "memory")
#define CPA_WAIT0()  asm volatile("cp.async.wait_group 0;" ::: "memory")

__device__ __forceinline__ void ldsm_x4(uint32_t& r0, uint32_t& r1, uint32_t& r2, uint32_t& r3,
                                        uint32_t a) {
    asm volatile("ldmatrix.sync.aligned.m8n8.x4.shared.b16 {%0,%1,%2,%3}, [%4];"
                 : "=r"(r0), "=r"(r1), "=r"(r2), "=r"(r3) : "r"(a));
}
__device__ __forceinline__ void mma16816(float* d, const uint32_t* a, const uint32_t* b) {
    asm volatile("mma.sync.aligned.m16n8k16.row.col.f32.f16.f16.f32 "
                 "{%0,%1,%2,%3}, {%4,%5,%6,%7}, {%8,%9}, {%0,%1,%2,%3};"
                 : "+f"(d[0]), "+f"(d[1]), "+f"(d[2]), "+f"(d[3])
                 : "r"(a[0]), "r"(a[1]), "r"(a[2]), "r"(a[3]), "r"(b[0]), "r"(b[1]));
}

// ---------------- prep: Wh^T fp16, per-node exp factors (fused combine for layer 1) -------
__global__ void __launch_bounds__(64) prep_kernel(const float* __restrict__ xa,
                                                  const float* __restrict__ xb,
                                                  const float* __restrict__ Wm,
                                                  const float* __restrict__ bv,
                                                  const float* __restrict__ av, int use_gx) {
    __shared__ float Ws[DH * DH];
    __shared__ float as_[2 * DH];
    __shared__ float bs[DH];
    int t = threadIdx.x;
    for (int k = t; k < DH * DH; k += 64) Ws[k] = Wm[k];
    if (t < DH) { as_[t] = av[t]; as_[DH + t] = av[DH + t]; bs[t] = bv[t]; }
    __syncthreads();

    int row = blockIdx.x * 64 + t;
    float x[DH];
    if (use_gx) {
        // fused combine: normalize K-split partials + relu
        const float* p0 = g_part + (size_t)row * DH;
        const float* p1 = g_part + (size_t)NN * DH + (size_t)row * DH;
        float inv = 1.0f / (g_den[row] + g_den[NN + row]);
#pragma unroll
        for (int q = 0; q < 16; q++) {
            float4 v0 = ((const float4*)p0)[q];
            float4 v1 = ((const float4*)p1)[q];
            x[4 * q]     = fmaxf((v0.x + v1.x) * inv, 0.f);
            x[4 * q + 1] = fmaxf((v0.y + v1.y) * inv, 0.f);
            x[4 * q + 2] = fmaxf((v0.z + v1.z) * inv, 0.f);
            x[4 * q + 3] = fmaxf((v0.w + v1.w) * inv, 0.f);
        }
    } else {
        const float* xr = row < NN / 2 ? xa + (size_t)row * DH
                                       : xb + (size_t)(row - NN / 2) * DH;
#pragma unroll
        for (int q = 0; q < 16; q++) {
            float4 v = ((const float4*)xr)[q];
            x[4 * q] = v.x; x[4 * q + 1] = v.y; x[4 * q + 2] = v.z; x[4 * q + 3] = v.w;
        }
    }

    float srcv = 0.f, dstv = 0.f;
    for (int i = 0; i < DH; i++) {
        const float4* w4 = (const float4*)(Ws + i * DH);
        float a0 = 0.f, a1 = 0.f, a2 = 0.f, a3 = 0.f;
#pragma unroll
        for (int q = 0; q < 16; q += 4) {
            float4 w;
            w = w4[q];     a0 = fmaf(x[4*q+3], w.w, fmaf(x[4*q+2], w.z, fmaf(x[4*q+1], w.y, fmaf(x[4*q], w.x, a0))));
            w = w4[q + 1]; a1 = fmaf(x[4*q+7], w.w, fmaf(x[4*q+6], w.z, fmaf(x[4*q+5], w.y, fmaf(x[4*q+4], w.x, a1))));
            w = w4[q + 2]; a2 = fmaf(x[4*q+11], w.w, fmaf(x[4*q+10], w.z, fmaf(x[4*q+9], w.y, fmaf(x[4*q+8], w.x, a2))));
            w = w4[q + 3]; a3 = fmaf(x[4*q+15], w.w, fmaf(x[4*q+14], w.z, fmaf(x[4*q+13], w.y, fmaf(x[4*q+12], w.x, a3))));
        }
        float wh = bs[i] + ((a0 + a1) + (a2 + a3));
        srcv = fmaf(wh, as_[i], srcv);
        dstv = fmaf(wh, as_[DH + i], dstv);
        g_WhT[(size_t)i * NN + row] = __half_as_ushort(__float2half_rn(wh));
    }

    __half2 Ah = __float2half2_rn(expf(srcv));
    __half2 Ch = __float2half2_rn(expf(0.2f * srcv));
    g_iAC[row] = make_uint2(*(uint32_t*)&Ah, *(uint32_t*)&Ch);
    g_jB[row] = __half_as_ushort(__float2half_rn(expf(dstv)));
    g_jD[row] = __half_as_ushort(__float2half_rn(expf(0.2f * dstv)));
}

// ---------------- weight-tile generation (half2) + fp32 row-sum ----------------
template<int L0>
__device__ __forceinline__ void gen_store(char* smemp, uint32_t wo, uint32_t wdst0, uint32_t wdst1,
                                          uint32_t A2, uint32_t C2,
                                          const uint4& B0, const uint4& B1,
                                          const uint4& D0, const uint4& D1,
                                          uint32_t bits_in, const int* vi,
                                          unsigned short* packdst, float& dsum) {
    uint32_t Bw[8] = {B0.x, B0.y, B0.z, B0.w, B1.x, B1.y, B1.z, B1.w};
    uint32_t Dw[8] = {D0.x, D0.y, D0.z, D0.w, D1.x, D1.y, D1.z, D1.w};
    uint32_t wv[8];
    uint32_t packbits = 0;
    __half2 A2h = *(__half2*)&A2, C2h = *(__half2*)&C2;
#pragma unroll
    for (int p = 0; p < 8; p++) {
        __half2 ab = __hmul2(A2h, *(__half2*)&Bw[p]);
        __half2 cd = __hmul2(C2h, *(__half2*)&Dw[p]);
        __half2 w = __hmax2(ab, cd);      // exp(leaky_relu(src+dst)) — exp is monotone
        uint32_t m;
        if (L0) {
            int v0 = vi[2 * p], v1 = vi[2 * p + 1];
            m = (v0 != 0 ? 0x0000FFFFu : 0u) | (v1 != 0 ? 0xFFFF0000u : 0u);
            packbits |= (v0 != 0 ? 1u : 0u) << (2 * p);
            packbits |= (v1 != 0 ? 1u : 0u) << (2 * p + 1);
        } else {
            uint32_t e = (bits_in >> (2 * p)) & 3u;
            uint32_t xm = (e * 0x8001u) & 0x10001u;
            m = xm * 0xFFFFu;
        }
        wv[p] = (*(uint32_t*)&w) & m;
    }
    // fp32 row-sum of the masked fp16 weights (softmax denominator)
    __half2 s01 = __hadd2(*(__half2*)&wv[0], *(__half2*)&wv[1]);
    __half2 s23 = __hadd2(*(__half2*)&wv[2], *(__half2*)&wv[3]);
    __half2 s45 = __hadd2(*(__half2*)&wv[4], *(__half2*)&wv[5]);
    __half2 s67 = __hadd2(*(__half2*)&wv[6], *(__half2*)&wv[7]);
    float2 f0 = __half22float2(__hadd2(s01, s23));
    float2 f1 = __half22float2(__hadd2(s45, s67));
    dsum += (f0.x + f0.y) + (f1.x + f1.y);

    *(uint4*)(smemp + wo + wdst0) = make_uint4(wv[0], wv[1], wv[2], wv[3]);
    *(uint4*)(smemp + wo + wdst1) = make_uint4(wv[4], wv[5], wv[6], wv[7]);
    if (L0) *packdst = (unsigned short)packbits;
}

// ---------------- attn: HMMA flash-GAT, 64x4096 per CTA ----------------
template<int L0>
__global__ void __launch_bounds__(TPB, 3) attn_mma(const int* __restrict__ adj) {
    extern __shared__ char smem[];
    uint32_t sb = smem_u32(smem);
    int t = threadIdx.x, wid = t >> 5, lane = t & 31;
    int tile = blockIdx.x >> 1, ks = blockIdx.x & 1;
    int i0 = tile * TILE_I, jbase = ks * KHALF;

    // ---- gen mapping: thread -> row i_loc, 16 j's at quarter jq16 ----
    int i_loc = t >> 2, jq16 = t & 3;
    int irow = i0 + i_loc;
    uint2 ac = g_iAC[irow];
    uint32_t wdst0 = SWZ((uint32_t)(i_loc * 128 + jq16 * 32));
    uint32_t wdst1 = SWZ((uint32_t)(i_loc * 128 + jq16 * 32 + 16));
    const uint4* pB = (const uint4*)(g_jB + jbase) + jq16 * 2;   // +8 per chunk
    const uint4* pD = (const uint4*)(g_jD + jbase) + jq16 * 2;
    const int4* pAdj = (const int4*)(adj + (size_t)irow * NN + jbase) + jq16 * 4;  // +16 per chunk
    unsigned short* pPack = g_adjp + (size_t)irow * 512 + (jbase >> 4) + jq16;     // +4 per chunk
    float dsum = 0.f;

    // ---- B staging (cp.async): 512 16B segs = 2/thread ----
    int s0 = t, s1 = t + 256;
    uint32_t bd0 = SWZ((uint32_t)((s0 >> 3) * 128 + (s0 & 7) * 16));
    uint32_t bd1 = SWZ((uint32_t)((s1 >> 3) * 128 + (s1 & 7) * 16));
    const unsigned short* bs0p = g_WhT + (size_t)(s0 >> 3) * NN + jbase + (s0 & 7) * 8;
    const unsigned short* bs1p = g_WhT + (size_t)(s1 >> 3) * NN + jbase + (s1 & 7) * 8;

    // ---- GEMM mapping: 8 warps = 4 M-tiles(16) x 2 N-halves(32) ----
    int wm = wid & 3, wn = wid >> 2;
    int lr = lane & 7, lsel = lane >> 3;
    float acc[4][4];
#pragma unroll
    for (int n = 0; n < 4; n++)
#pragma unroll
        for (int p = 0; p < 4; p++) acc[n][p] = 0.f;

    // ---- prefetch regs for chunk 0 ----
    uint4 Bq0 = pB[0], Bq1 = pB[1], Dq0 = pD[0], Dq1 = pD[1];
    uint32_t bits = 0;
    int4 rv[4];
    if (L0) {
        rv[0] = __ldcs(pAdj + 0); rv[1] = __ldcs(pAdj + 1);
        rv[2] = __ldcs(pAdj + 2); rv[3] = __ldcs(pAdj + 3);
    } else bits = pPack[0];

    // ---- stage chunk 0 ----
    CPA16(sb + BOFF0 + bd0, bs0p);
    CPA16(sb + BOFF0 + bd1, bs1p);
    CPA_COMMIT();
    gen_store<L0>(smem, WOFF0, wdst0, wdst1, ac.x, ac.y, Bq0, Bq1, Dq0, Dq1,
                  bits, (const int*)rv, pPack, dsum);
    Bq0 = pB[8]; Bq1 = pB[9]; Dq0 = pD[8]; Dq1 = pD[9];
    if (L0) {
        rv[0] = __ldcs(pAdj + 16); rv[1] = __ldcs(pAdj + 17);
        rv[2] = __ldcs(pAdj + 18); rv[3] = __ldcs(pAdj + 19);
    } else bits = pPack[4];
    CPA_WAIT0();
    __syncthreads();

    for (int c = 0; c < NCH; c++) {
        int buf = c & 1;
        if (c + 1 < NCH) {
            int nb = buf ^ 1;
            uint32_t bo = nb ? BOFF1 : BOFF0, wo = nb ? WOFF1 : WOFF0;
            CPA16(sb + bo + bd0, bs0p + (c + 1) * 64);
            CPA16(sb + bo + bd1, bs1p + (c + 1) * 64);
            CPA_COMMIT();
            gen_store<L0>(smem, wo, wdst0, wdst1, ac.x, ac.y, Bq0, Bq1, Dq0, Dq1,
                          bits, (const int*)rv, pPack + (c + 1) * 4, dsum);
            if (c + 2 < NCH) {
                Bq0 = pB[(c + 2) * 8]; Bq1 = pB[(c + 2) * 8 + 1];
                Dq0 = pD[(c + 2) * 8]; Dq1 = pD[(c + 2) * 8 + 1];
                if (L0) {
                    rv[0] = __ldcs(pAdj + (c + 2) * 16);     rv[1] = __ldcs(pAdj + (c + 2) * 16 + 1);
                    rv[2] = __ldcs(pAdj + (c + 2) * 16 + 2); rv[3] = __ldcs(pAdj + (c + 2) * 16 + 3);
                } else bits = pPack[(c + 2) * 4];
            }
        }

        // ---- GEMM on chunk c ----
        uint32_t wbase = sb + (buf ? WOFF1 : WOFF0);
        uint32_t bbase = sb + (buf ? BOFF1 : BOFF0);
#pragma unroll
        for (int k = 0; k < 4; k++) {
            uint32_t af[4], bf[8];
            uint32_t a_adr = wbase + SWZ((uint32_t)((wm * 16 + lr + (lsel & 1) * 8) * 128 + ((lsel >> 1) * 8 + k * 16) * 2));
            ldsm_x4(af[0], af[1], af[2], af[3], a_adr);
#pragma unroll
            for (int p = 0; p < 2; p++) {
                uint32_t b_adr = bbase + SWZ((uint32_t)((wn * 32 + p * 16 + lr + (lsel >> 1) * 8) * 128 + ((lsel & 1) * 8 + k * 16) * 2));
                ldsm_x4(bf[p * 4 + 0], bf[p * 4 + 1], bf[p * 4 + 2], bf[p * 4 + 3], b_adr);
            }
            mma16816(acc[0], af, bf + 0);
            mma16816(acc[1], af, bf + 2);
            mma16816(acc[2], af, bf + 4);
            mma16816(acc[3], af, bf + 6);
        }
        CPA_WAIT0();
        __syncthreads();
    }

    // ---- denominator: reduce over the 4 gen threads of each row ----
    dsum += __shfl_xor_sync(0xffffffffu, dsum, 1);
    dsum += __shfl_xor_sync(0xffffffffu, dsum, 2);
    if (jq16 == 0) g_den[(size_t)ks * NN + irow] = dsum;

    // ---- epilogue: write partial numerators ----
    int row0 = i0 + wm * 16 + (lane >> 2);
    float* base = g_part + (size_t)ks * NN * DH;
#pragma unroll
    for (int nt = 0; nt < 4; nt++) {
        int col = wn * 32 + nt * 8 + (lane & 3) * 2;
        *(float2*)(base + (size_t)row0 * DH + col) = make_float2(acc[nt][0], acc[nt][1]);
        *(float2*)(base + (size_t)(row0 + 8) * DH + col) = make_float2(acc[nt][2], acc[nt][3]);
    }
}

// ---------------- final: fused combine + out = x @ out_w^T + out_b ----------------
__global__ void __launch_bounds__(64) final_kernel(const float* __restrict__ Wm,
                                                   const float* __restrict__ bv,
                                                   float* __restrict__ out) {
    __shared__ float Ws[DH * DH];
    __shared__ float bs[DH];
    int t = threadIdx.x;
    for (int k = t; k < DH * DH; k += 64) Ws[k] = Wm[k];
    if (t < DH) bs[t] = bv[t];
    __syncthreads();

    int row = blockIdx.x * 64 + t;
    const float* p0 = g_part + (size_t)row * DH;
    const float* p1 = g_part + (size_t)NN * DH + (size_t)row * DH;
    float inv = 1.0f / (g_den[row] + g_den[NN + row]);
    float x[DH];
#pragma unroll
    for (int q = 0; q < 16; q++) {
        float4 v0 = ((const float4*)p0)[q];
        float4 v1 = ((const float4*)p1)[q];
        x[4 * q]     = fmaxf((v0.x + v1.x) * inv, 0.f);
        x[4 * q + 1] = fmaxf((v0.y + v1.y) * inv, 0.f);
        x[4 * q + 2] = fmaxf((v0.z + v1.z) * inv, 0.f);
        x[4 * q + 3] = fmaxf((v0.w + v1.w) * inv, 0.f);
    }

    float* orow = out + (size_t)row * DH;
    for (int i = 0; i < DH; i += 4) {
        float4 res;
#pragma unroll
        for (int u = 0; u < 4; u++) {
            const float4* w4 = (const float4*)(Ws + (i + u) * DH);
            float a0 = 0.f, a1 = 0.f, a2 = 0.f, a3 = 0.f;
#pragma unroll
            for (int q = 0; q < 16; q += 4) {
                float4 w;
                w = w4[q];     a0 = fmaf(x[4*q+3], w.w, fmaf(x[4*q+2], w.z, fmaf(x[4*q+1], w.y, fmaf(x[4*q], w.x, a0))));
                w = w4[q + 1]; a1 = fmaf(x[4*q+7], w.w, fmaf(x[4*q+6], w.z, fmaf(x[4*q+5], w.y, fmaf(x[4*q+4], w.x, a1))));
                w = w4[q + 2]; a2 = fmaf(x[4*q+11], w.w, fmaf(x[4*q+10], w.z, fmaf(x[4*q+9], w.y, fmaf(x[4*q+8], w.x, a2))));
                w = w4[q + 3]; a3 = fmaf(x[4*q+15], w.w, fmaf(x[4*q+14], w.z, fmaf(x[4*q+13], w.y, fmaf(x[4*q+12], w.x, a3))));
            }
            ((float*)&res)[u] = bs[i + u] + ((a0 + a1) + (a2 + a3));
        }
        ((float4*)orow)[i >> 2] = res;
    }
}

// ---------------- launch ----------------
extern "C" void kernel_launch(void* const* d_in, const int* in_sizes, int n_in,
                              void* d_out, int out_size) {
    const int*   adj  = (const int*)d_in[0];
    const float* user = (const float*)d_in[1];
    const float* item = (const float*)d_in[2];
    const float* W0   = (const float*)d_in[3];
    const float* b0   = (const float*)d_in[4];
    const float* a0   = (const float*)d_in[5];
    const float* W1   = (const float*)d_in[6];
    const float* b1   = (const float*)d_in[7];
    const float* a1   = (const float*)d_in[8];
    const float* ow   = (const float*)d_in[9];
    const float* ob   = (const float*)d_in[10];

    cudaFuncSetAttribute(attn_mma<1>, cudaFuncAttributeMaxDynamicSharedMemorySize, SMEM_BYTES);
    cudaFuncSetAttribute(attn_mma<0>, cudaFuncAttributeMaxDynamicSharedMemorySize, SMEM_BYTES);

    prep_kernel<<<NN / 64, 64>>>(user, item, W0, b0, a0, 0);
    attn_mma<1><<<(NN / TILE_I) * KSPLIT, TPB, SMEM_BYTES>>>(adj);   // fused: packs adj bits
    prep_kernel<<<NN / 64, 64>>>(nullptr, nullptr, W1, b1, a1, 1);   // fused combine
    attn_mma<0><<<(NN / TILE_I) * KSPLIT, TPB, SMEM_BYTES>>>(adj);   // reads packed bits
    final_kernel<<<NN / 64, 64>>>(ow, ob, (float*)d_out);            // fused combine
}

// round 14
// speedup vs baseline: 2.2136x; 1.0785x over previous
#include <cuda_runtime.h>
#include <cuda_fp16.h>
#include <stdint.h>

#define NN 8192
#define DH 64
#define KC 64              // j's per chunk
#define KSPLIT 2
#define KHALF (NN / KSPLIT)
#define NCH (KHALF / KC)   // 64 chunks
#define TPB 256
#define TILE_I 64
// smem: W tile 64x64 fp16 (8KB) x2, B tile 64x64 fp16 (8KB) x2
#define WOFF0 0
#define WOFF1 8192
#define BOFF0 16384
#define BOFF1 24576
#define SMEM_BYTES 32768

// ---------------- device scratch ----------------
__device__ unsigned short g_adjp[NN * 512];    // packed adjacency bits (8MB)
__device__ unsigned short g_WhT[DH * NN];      // Wh^T fp16 [64][8192]
__device__ uint2 g_iAC[NN];                    // {half2(exp(src)), half2(exp(.2src))}
__device__ unsigned short g_jB[NN];            // half exp(dst)
__device__ unsigned short g_jD[NN];            // half exp(.2 dst)
__device__ float g_part[KSPLIT * NN * DH];     // K-split partial numerators
__device__ float g_den[KSPLIT * NN];           // K-split partial denominators

// ---------------- helpers ----------------
__device__ __forceinline__ uint32_t smem_u32(const void* p) {
    uint32_t a;
    asm("{ .reg .u64 t; cvta.to.shared.u64 t, %1; cvt.u32.u64 %0, t; }" : "=r"(a) : "l"(p));
    return a;
}
#define SWZ(off) ((off) ^ (((off) >> 3) & 0x70))

#define CPA16(d, s) asm volatile("cp.async.cg.shared.global [%0], [%1], 16;" :: "r"(d), "l"(s))
#define CPA_COMMIT() asm volatile("cp.async.commit_group;" ::: "memory")
#define CPA_WAIT0()  asm volatile("cp.async.wait_group 0;" ::: "memory")

__device__ __forceinline__ void ldsm_x4(uint32_t& r0, uint32_t& r1, uint32_t& r2, uint32_t& r3,
                                        uint32_t a) {
    asm volatile("ldmatrix.sync.aligned.m8n8.x4.shared.b16 {%0,%1,%2,%3}, [%4];"
                 : "=r"(r0), "=r"(r1), "=r"(r2), "=r"(r3) : "r"(a));
}
__device__ __forceinline__ void mma16816(float* d, const uint32_t* a, const uint32_t* b) {
    asm volatile("mma.sync.aligned.m16n8k16.row.col.f32.f16.f16.f32 "
                 "{%0,%1,%2,%3}, {%4,%5,%6,%7}, {%8,%9}, {%0,%1,%2,%3};"
                 : "+f"(d[0]), "+f"(d[1]), "+f"(d[2]), "+f"(d[3])
                 : "r"(a[0]), "r"(a[1]), "r"(a[2]), "r"(a[3]), "r"(b[0]), "r"(b[1]));
}

// ---------------- prep: x in smem (broadcast), W row in regs ----------------
// 256 thr: group g = t>>6 owns rows g*16..g*16+15; i = t&63 owns output column i.
__global__ void __launch_bounds__(256) prep_kernel(const float* __restrict__ xa,
                                                   const float* __restrict__ xb,
                                                   const float* __restrict__ Wm,
                                                   const float* __restrict__ bv,
                                                   const float* __restrict__ av, int use_gx) {
    __shared__ float xs[64][64];       // 16 KB input rows
    __shared__ float whs[64][65];      // 16.6 KB fp32 Wh (padded)
    __shared__ float as_[2 * DH];
    __shared__ float bsh[DH];
    __shared__ float inv_s[64];
    int t = threadIdx.x;
    int row0 = blockIdx.x * 64;

    if (t < 2 * DH) as_[t] = av[t];
    if (t < DH) bsh[t] = bv[t];
    if (use_gx && t < 64) {
        int row = row0 + t;
        inv_s[t] = 1.0f / (g_den[row] + g_den[NN + row]);
    }
    __syncthreads();

    // ---- stage xs: thread (r = t>>2, q = t&3) covers floats q*16..q*16+15 ----
    {
        int r = t >> 2, q = t & 3;
        int row = row0 + r;
        if (use_gx) {
            const float4* p0 = (const float4*)(g_part + (size_t)row * DH) + q * 4;
            const float4* p1 = (const float4*)(g_part + (size_t)(NN + row) * DH) + q * 4;
            float inv = inv_s[r];
#pragma unroll
            for (int k = 0; k < 4; k++) {
                float4 v0 = p0[k], v1 = p1[k];
                xs[r][q * 16 + 4 * k + 0] = fmaxf((v0.x + v1.x) * inv, 0.f);
                xs[r][q * 16 + 4 * k + 1] = fmaxf((v0.y + v1.y) * inv, 0.f);
                xs[r][q * 16 + 4 * k + 2] = fmaxf((v0.z + v1.z) * inv, 0.f);
                xs[r][q * 16 + 4 * k + 3] = fmaxf((v0.w + v1.w) * inv, 0.f);
            }
        } else {
            const float* xr = row < NN / 2 ? xa + (size_t)row * DH
                                           : xb + (size_t)(row - NN / 2) * DH;
#pragma unroll
            for (int k = 0; k < 4; k++) {
                float4 v = ((const float4*)xr)[q * 4 + k];
                xs[r][q * 16 + 4 * k + 0] = v.x;
                xs[r][q * 16 + 4 * k + 1] = v.y;
                xs[r][q * 16 + 4 * k + 2] = v.z;
                xs[r][q * 16 + 4 * k + 3] = v.w;
            }
        }
    }

    // ---- W row i into registers ----
    int i = t & 63, g = t >> 6;
    float Wr[64];
#pragma unroll
    for (int k = 0; k < 16; k++) {
        float4 w = ((const float4*)(Wm + (size_t)i * DH))[k];
        Wr[4 * k] = w.x; Wr[4 * k + 1] = w.y; Wr[4 * k + 2] = w.z; Wr[4 * k + 3] = w.w;
    }
    __syncthreads();

    // ---- compute Wh for 16 rows (xs reads are warp-broadcast) ----
    float bias = bsh[i];
    int rbase = g * 16;
#pragma unroll
    for (int r = 0; r < 16; r++) {
        int rr = rbase + r;
        float a0 = 0.f, a1 = 0.f, a2 = 0.f, a3 = 0.f;
#pragma unroll
        for (int k = 0; k < 16; k++) {
            float4 xv = *(const float4*)&xs[rr][4 * k];
            a0 = fmaf(Wr[4 * k + 0], xv.x, a0);
            a1 = fmaf(Wr[4 * k + 1], xv.y, a1);
            a2 = fmaf(Wr[4 * k + 2], xv.z, a2);
            a3 = fmaf(Wr[4 * k + 3], xv.w, a3);
        }
        whs[rr][i] = bias + ((a0 + a1) + (a2 + a3));
    }
    __syncthreads();

    // ---- write Wh^T fp16 to global (coalesced 32B per thread) ----
    {
        int ii = t >> 2, rq = t & 3;
        uint32_t packed[8];
#pragma unroll
        for (int k = 0; k < 8; k++) {
            __half2 h = __floats2half2_rn(whs[rq * 16 + 2 * k][ii], whs[rq * 16 + 2 * k + 1][ii]);
            packed[k] = *(uint32_t*)&h;
        }
        uint4* dst = (uint4*)(g_WhT + (size_t)ii * NN + row0 + rq * 16);
        dst[0] = make_uint4(packed[0], packed[1], packed[2], packed[3]);
        dst[1] = make_uint4(packed[4], packed[5], packed[6], packed[7]);
    }

    // ---- src/dst: 4 threads/row, fp32, shfl reduce ----
    {
        int r = t >> 2, q = t & 3;
        float sv = 0.f, dv = 0.f;
#pragma unroll
        for (int k = 0; k < 16; k++) {
            int ii = q * 16 + k;
            float wh = whs[r][ii];
            sv = fmaf(wh, as_[ii], sv);
            dv = fmaf(wh, as_[DH + ii], dv);
        }
        sv += __shfl_xor_sync(0xffffffffu, sv, 1);
        sv += __shfl_xor_sync(0xffffffffu, sv, 2);
        dv += __shfl_xor_sync(0xffffffffu, dv, 1);
        dv += __shfl_xor_sync(0xffffffffu, dv, 2);
        if (q == 0) {
            int row = row0 + r;
            __half2 Ah = __float2half2_rn(expf(sv));
            __half2 Ch = __float2half2_rn(expf(0.2f * sv));
            g_iAC[row] = make_uint2(*(uint32_t*)&Ah, *(uint32_t*)&Ch);
            g_jB[row] = __half_as_ushort(__float2half_rn(expf(dv)));
            g_jD[row] = __half_as_ushort(__float2half_rn(expf(0.2f * dv)));
        }
    }
}

// ---------------- weight-tile generation (half2) + fp32 row-sum ----------------
template<int L0>
__device__ __forceinline__ void gen_store(char* smemp, uint32_t wo, uint32_t wdst0, uint32_t wdst1,
                                          uint32_t A2, uint32_t C2,
                                          const uint4& B0, const uint4& B1,
                                          const uint4& D0, const uint4& D1,
                                          uint32_t bits_in, const int* vi,
                                          unsigned short* packdst, float& dsum) {
    uint32_t Bw[8] = {B0.x, B0.y, B0.z, B0.w, B1.x, B1.y, B1.z, B1.w};
    uint32_t Dw[8] = {D0.x, D0.y, D0.z, D0.w, D1.x, D1.y, D1.z, D1.w};
    uint32_t wv[8];
    uint32_t packbits = 0;
    __half2 A2h = *(__half2*)&A2, C2h = *(__half2*)&C2;
#pragma unroll
    for (int p = 0; p < 8; p++) {
        __half2 ab = __hmul2(A2h, *(__half2*)&Bw[p]);
        __half2 cd = __hmul2(C2h, *(__half2*)&Dw[p]);
        __half2 w = __hmax2(ab, cd);      // exp(leaky_relu(src+dst)) — exp is monotone
        uint32_t m;
        if (L0) {
            int v0 = vi[2 * p], v1 = vi[2 * p + 1];
            m = (v0 != 0 ? 0x0000FFFFu : 0u) | (v1 != 0 ? 0xFFFF0000u : 0u);
            packbits |= (v0 != 0 ? 1u : 0u) << (2 * p);
            packbits |= (v1 != 0 ? 1u : 0u) << (2 * p + 1);
        } else {
            uint32_t e = (bits_in >> (2 * p)) & 3u;
            uint32_t xm = (e * 0x8001u) & 0x10001u;
            m = xm * 0xFFFFu;
        }
        wv[p] = (*(uint32_t*)&w) & m;
    }
    // fp32 row-sum of the masked fp16 weights (softmax denominator)
    __half2 s01 = __hadd2(*(__half2*)&wv[0], *(__half2*)&wv[1]);
    __half2 s23 = __hadd2(*(__half2*)&wv[2], *(__half2*)&wv[3]);
    __half2 s45 = __hadd2(*(__half2*)&wv[4], *(__half2*)&wv[5]);
    __half2 s67 = __hadd2(*(__half2*)&wv[6], *(__half2*)&wv[7]);
    float2 f0 = __half22float2(__hadd2(s01, s23));
    float2 f1 = __half22float2(__hadd2(s45, s67));
    dsum += (f0.x + f0.y) + (f1.x + f1.y);

    *(uint4*)(smemp + wo + wdst0) = make_uint4(wv[0], wv[1], wv[2], wv[3]);
    *(uint4*)(smemp + wo + wdst1) = make_uint4(wv[4], wv[5], wv[6], wv[7]);
    if (L0) *packdst = (unsigned short)packbits;
}

// ---------------- attn: HMMA flash-GAT, 64x4096 per CTA (unchanged from R13) ----------------
template<int L0>
__global__ void __launch_bounds__(TPB, 3) attn_mma(const int* __restrict__ adj) {
    extern __shared__ char smem[];
    uint32_t sb = smem_u32(smem);
    int t = threadIdx.x, wid = t >> 5, lane = t & 31;
    int tile = blockIdx.x >> 1, ks = blockIdx.x & 1;
    int i0 = tile * TILE_I, jbase = ks * KHALF;

    int i_loc = t >> 2, jq16 = t & 3;
    int irow = i0 + i_loc;
    uint2 ac = g_iAC[irow];
    uint32_t wdst0 = SWZ((uint32_t)(i_loc * 128 + jq16 * 32));
    uint32_t wdst1 = SWZ((uint32_t)(i_loc * 128 + jq16 * 32 + 16));
    const uint4* pB = (const uint4*)(g_jB + jbase) + jq16 * 2;
    const uint4* pD = (const uint4*)(g_jD + jbase) + jq16 * 2;
    const int4* pAdj = (const int4*)(adj + (size_t)irow * NN + jbase) + jq16 * 4;
    unsigned short* pPack = g_adjp + (size_t)irow * 512 + (jbase >> 4) + jq16;
    float dsum = 0.f;

    int s0 = t, s1 = t + 256;
    uint32_t bd0 = SWZ((uint32_t)((s0 >> 3) * 128 + (s0 & 7) * 16));
    uint32_t bd1 = SWZ((uint32_t)((s1 >> 3) * 128 + (s1 & 7) * 16));
    const unsigned short* bs0p = g_WhT + (size_t)(s0 >> 3) * NN + jbase + (s0 & 7) * 8;
    const unsigned short* bs1p = g_WhT + (size_t)(s1 >> 3) * NN + jbase + (s1 & 7) * 8;

    int wm = wid & 3, wn = wid >> 2;
    int lr = lane & 7, lsel = lane >> 3;
    float acc[4][4];
#pragma unroll
    for (int n = 0; n < 4; n++)
#pragma unroll
        for (int p = 0; p < 4; p++) acc[n][p] = 0.f;

    uint4 Bq0 = pB[0], Bq1 = pB[1], Dq0 = pD[0], Dq1 = pD[1];
    uint32_t bits = 0;
    int4 rv[4];
    if (L0) {
        rv[0] = __ldcs(pAdj + 0); rv[1] = __ldcs(pAdj + 1);
        rv[2] = __ldcs(pAdj + 2); rv[3] = __ldcs(pAdj + 3);
    } else bits = pPack[0];

    CPA16(sb + BOFF0 + bd0, bs0p);
    CPA16(sb + BOFF0 + bd1, bs1p);
    CPA_COMMIT();
    gen_store<L0>(smem, WOFF0, wdst0, wdst1, ac.x, ac.y, Bq0, Bq1, Dq0, Dq1,
                  bits, (const int*)rv, pPack, dsum);
    Bq0 = pB[8]; Bq1 = pB[9]; Dq0 = pD[8]; Dq1 = pD[9];
    if (L0) {
        rv[0] = __ldcs(pAdj + 16); rv[1] = __ldcs(pAdj + 17);
        rv[2] = __ldcs(pAdj + 18); rv[3] = __ldcs(pAdj + 19);
    } else bits = pPack[4];
    CPA_WAIT0();
    __syncthreads();

    for (int c = 0; c < NCH; c++) {
        int buf = c & 1;
        if (c + 1 < NCH) {
            int nb = buf ^ 1;
            uint32_t bo = nb ? BOFF1 : BOFF0, wo = nb ? WOFF1 : WOFF0;
            CPA16(sb + bo + bd0, bs0p + (c + 1) * 64);
            CPA16(sb + bo + bd1, bs1p + (c + 1) * 64);
            CPA_COMMIT();
            gen_store<L0>(smem, wo, wdst0, wdst1, ac.x, ac.y, Bq0, Bq1, Dq0, Dq1,
                          bits, (const int*)rv, pPack + (c + 1) * 4, dsum);
            if (c + 2 < NCH) {
                Bq0 = pB[(c + 2) * 8]; Bq1 = pB[(c + 2) * 8 + 1];
                Dq0 = pD[(c + 2) * 8]; Dq1 = pD[(c + 2) * 8 + 1];
                if (L0) {
                    rv[0] = __ldcs(pAdj + (c + 2) * 16);     rv[1] = __ldcs(pAdj + (c + 2) * 16 + 1);
                    rv[2] = __ldcs(pAdj + (c + 2) * 16 + 2); rv[3] = __ldcs(pAdj + (c + 2) * 16 + 3);
                } else bits = pPack[(c + 2) * 4];
            }
        }

        uint32_t wbase = sb + (buf ? WOFF1 : WOFF0);
        uint32_t bbase = sb + (buf ? BOFF1 : BOFF0);
#pragma unroll
        for (int k = 0; k < 4; k++) {
            uint32_t af[4], bf[8];
            uint32_t a_adr = wbase + SWZ((uint32_t)((wm * 16 + lr + (lsel & 1) * 8) * 128 + ((lsel >> 1) * 8 + k * 16) * 2));
            ldsm_x4(af[0], af[1], af[2], af[3], a_adr);
#pragma unroll
            for (int p = 0; p < 2; p++) {
                uint32_t b_adr = bbase + SWZ((uint32_t)((wn * 32 + p * 16 + lr + (lsel >> 1) * 8) * 128 + ((lsel & 1) * 8 + k * 16) * 2));
                ldsm_x4(bf[p * 4 + 0], bf[p * 4 + 1], bf[p * 4 + 2], bf[p * 4 + 3], b_adr);
            }
            mma16816(acc[0], af, bf + 0);
            mma16816(acc[1], af, bf + 2);
            mma16816(acc[2], af, bf + 4);
            mma16816(acc[3], af, bf + 6);
        }
        CPA_WAIT0();
        __syncthreads();
    }

    dsum += __shfl_xor_sync(0xffffffffu, dsum, 1);
    dsum += __shfl_xor_sync(0xffffffffu, dsum, 2);
    if (jq16 == 0) g_den[(size_t)ks * NN + irow] = dsum;

    int row0 = i0 + wm * 16 + (lane >> 2);
    float* base = g_part + (size_t)ks * NN * DH;
#pragma unroll
    for (int nt = 0; nt < 4; nt++) {
        int col = wn * 32 + nt * 8 + (lane & 3) * 2;
        *(float2*)(base + (size_t)row0 * DH + col) = make_float2(acc[nt][0], acc[nt][1]);
        *(float2*)(base + (size_t)(row0 + 8) * DH + col) = make_float2(acc[nt][2], acc[nt][3]);
    }
}

// ---------------- final: fused combine + out = x @ out_w^T + out_b (reg-W dataflow) -------
__global__ void __launch_bounds__(256) final_kernel(const float* __restrict__ Wm,
                                                    const float* __restrict__ bv,
                                                    float* __restrict__ out) {
    __shared__ float xs[64][64];
    __shared__ float bsh[DH];
    __shared__ float inv_s[64];
    int t = threadIdx.x;
    int row0 = blockIdx.x * 64;
    if (t < DH) bsh[t] = bv[t];
    if (t < 64) {
        int row = row0 + t;
        inv_s[t] = 1.0f / (g_den[row] + g_den[NN + row]);
    }
    __syncthreads();

    {
        int r = t >> 2, q = t & 3;
        int row = row0 + r;
        const float4* p0 = (const float4*)(g_part + (size_t)row * DH) + q * 4;
        const float4* p1 = (const float4*)(g_part + (size_t)(NN + row) * DH) + q * 4;
        float inv = inv_s[r];
#pragma unroll
        for (int k = 0; k < 4; k++) {
            float4 v0 = p0[k], v1 = p1[k];
            xs[r][q * 16 + 4 * k + 0] = fmaxf((v0.x + v1.x) * inv, 0.f);
            xs[r][q * 16 + 4 * k + 1] = fmaxf((v0.y + v1.y) * inv, 0.f);
            xs[r][q * 16 + 4 * k + 2] = fmaxf((v0.z + v1.z) * inv, 0.f);
            xs[r][q * 16 + 4 * k + 3] = fmaxf((v0.w + v1.w) * inv, 0.f);
        }
    }

    int i = t & 63, g = t >> 6;
    float Wr[64];
#pragma unroll
    for (int k = 0; k < 16; k++) {
        float4 w = ((const float4*)(Wm + (size_t)i * DH))[k];
        Wr[4 * k] = w.x; Wr[4 * k + 1] = w.y; Wr[4 * k + 2] = w.z; Wr[4 * k + 3] = w.w;
    }
    __syncthreads();

    float bias = bsh[i];
    int rbase = g * 16;
#pragma unroll
    for (int r = 0; r < 16; r++) {
        int rr = rbase + r;
        float a0 = 0.f, a1 = 0.f, a2 = 0.f, a3 = 0.f;
#pragma unroll
        for (int k = 0; k < 16; k++) {
            float4 xv = *(const float4*)&xs[rr][4 * k];
            a0 = fmaf(Wr[4 * k + 0], xv.x, a0);
            a1 = fmaf(Wr[4 * k + 1], xv.y, a1);
            a2 = fmaf(Wr[4 * k + 2], xv.z, a2);
            a3 = fmaf(Wr[4 * k + 3], xv.w, a3);
        }
        out[(size_t)(row0 + rr) * DH + i] = bias + ((a0 + a1) + (a2 + a3));
    }
}

// ---------------- launch ----------------
extern "C" void kernel_launch(void* const* d_in, const int* in_sizes, int n_in,
                              void* d_out, int out_size) {
    const int*   adj  = (const int*)d_in[0];
    const float* user = (const float*)d_in[1];
    const float* item = (const float*)d_in[2];
    const float* W0   = (const float*)d_in[3];
    const float* b0   = (const float*)d_in[4];
    const float* a0   = (const float*)d_in[5];
    const float* W1   = (const float*)d_in[6];
    const float* b1   = (const float*)d_in[7];
    const float* a1   = (const float*)d_in[8];
    const float* ow   = (const float*)d_in[9];
    const float* ob   = (const float*)d_in[10];

    cudaFuncSetAttribute(attn_mma<1>, cudaFuncAttributeMaxDynamicSharedMemorySize, SMEM_BYTES);
    cudaFuncSetAttribute(attn_mma<0>, cudaFuncAttributeMaxDynamicSharedMemorySize, SMEM_BYTES);

    prep_kernel<<<NN / 64, 256>>>(user, item, W0, b0, a0, 0);
    attn_mma<1><<<(NN / TILE_I) * KSPLIT, TPB, SMEM_BYTES>>>(adj);   // fused: packs adj bits
    prep_kernel<<<NN / 64, 256>>>(nullptr, nullptr, W1, b1, a1, 1);  // fused combine
    attn_mma<0><<<(NN / TILE_I) * KSPLIT, TPB, SMEM_BYTES>>>(adj);   // reads packed bits
    final_kernel<<<NN / 64, 256>>>(ow, ob, (float*)d_out);           // fused combine
}